// round 1
// baseline (speedup 1.0000x reference)
#include <cuda_runtime.h>
#include <cuda_bf16.h>
#include <math.h>

#define N_NODES 100000
#define N_EDGES 3200000
#define N_FEAT  512
#define N_HID   256
#define N_CLASS 40
#define K_HOPS  10

// ---------------- scratch (no cudaMalloc allowed) ----------------
__device__ float g_h1[(size_t)N_NODES * N_HID];            // 102.4 MB
__device__ float g_xs[(size_t)(K_HOPS + 1) * N_NODES * N_CLASS]; // 176 MB
__device__ int   g_rowptr[N_NODES + 1];
__device__ int   g_count[N_NODES];
__device__ int   g_cursor[N_NODES];
__device__ int   g_cols[N_EDGES];
__device__ float g_wsorted[N_EDGES];

// ---------------- GEMM1: relu(feature @ W1 + b1) -> g_h1 ----------------
// BM=128, BN=64, BK=16, 256 threads, 8x4 register tile.
__global__ void gemm1_kernel(const float* __restrict__ A,
                             const float* __restrict__ B,
                             const float* __restrict__ bias) {
    __shared__ float As[16][132];   // [k][m], padded stride
    __shared__ float Bs[16][64];    // [k][n]

    const int tid  = threadIdx.x;
    const int bm   = blockIdx.x * 128;
    const int bn   = blockIdx.y * 64;
    const int mIdx = tid >> 4;      // 0..15 -> rows m0 = mIdx*8
    const int nIdx = tid & 15;      // 0..15 -> cols n0 = nIdx*4

    float acc[8][4];
#pragma unroll
    for (int i = 0; i < 8; i++)
#pragma unroll
        for (int j = 0; j < 4; j++) acc[i][j] = 0.f;

    for (int kt = 0; kt < N_FEAT; kt += 16) {
        // load A tile (128x16) as 512 float4, 2 per thread, transposed into As
#pragma unroll
        for (int r = 0; r < 2; r++) {
            int i  = tid + r * 256;
            int m  = i >> 2;
            int k4 = (i & 3) * 4;
            int gm = bm + m;
            float4 v = make_float4(0.f, 0.f, 0.f, 0.f);
            if (gm < N_NODES)
                v = *(const float4*)(A + (size_t)gm * N_FEAT + kt + k4);
            As[k4 + 0][m] = v.x;
            As[k4 + 1][m] = v.y;
            As[k4 + 2][m] = v.z;
            As[k4 + 3][m] = v.w;
        }
        // load B tile (16x64), 1 float4 per thread
        {
            int kr = tid >> 4;
            int c4 = (tid & 15) * 4;
            float4 v = *(const float4*)(B + (size_t)(kt + kr) * N_HID + bn + c4);
            *(float4*)&Bs[kr][c4] = v;
        }
        __syncthreads();

#pragma unroll
        for (int k = 0; k < 16; k++) {
            float ra[8], rb[4];
#pragma unroll
            for (int i = 0; i < 8; i++) ra[i] = As[k][mIdx * 8 + i];
#pragma unroll
            for (int j = 0; j < 4; j++) rb[j] = Bs[k][nIdx * 4 + j];
#pragma unroll
            for (int i = 0; i < 8; i++)
#pragma unroll
                for (int j = 0; j < 4; j++) acc[i][j] += ra[i] * rb[j];
        }
        __syncthreads();
    }

#pragma unroll
    for (int i = 0; i < 8; i++) {
        int gm = bm + mIdx * 8 + i;
        if (gm < N_NODES) {
#pragma unroll
            for (int j = 0; j < 4; j++) {
                int gn = bn + nIdx * 4 + j;
                float v = acc[i][j] + bias[gn];
                g_h1[(size_t)gm * N_HID + gn] = fmaxf(v, 0.f);
            }
        }
    }
}

// ---------------- GEMM2: g_h1 @ W2 + b2 -> g_xs plane 0 ----------------
// 64 rows/block, 256 threads; thread = (row, quarter of 10 channels)
__global__ void gemm2_kernel(const float* __restrict__ W2,
                             const float* __restrict__ b2) {
    __shared__ float As[64][65];
    __shared__ float W2s[64 * N_CLASS];

    const int tid = threadIdx.x;
    const int bm  = blockIdx.x * 64;
    const int row = tid >> 2;       // 0..63
    const int q   = tid & 3;        // channel group q*10

    float acc[10];
#pragma unroll
    for (int j = 0; j < 10; j++) acc[j] = 0.f;

    for (int kb = 0; kb < N_HID; kb += 64) {
        // load As (64x64): 1024 float4, 4 per thread
#pragma unroll
        for (int r = 0; r < 4; r++) {
            int i  = tid + r * 256;
            int rr = i >> 4;
            int c4 = (i & 15) * 4;
            int gm = bm + rr;
            float4 v = make_float4(0.f, 0.f, 0.f, 0.f);
            if (gm < N_NODES)
                v = *(const float4*)(g_h1 + (size_t)gm * N_HID + kb + c4);
            As[rr][c4 + 0] = v.x;
            As[rr][c4 + 1] = v.y;
            As[rr][c4 + 2] = v.z;
            As[rr][c4 + 3] = v.w;
        }
        // load W2 chunk (64x40 = 2560 floats, contiguous), 10 per thread
#pragma unroll
        for (int r = 0; r < 10; r++) {
            int e = tid + r * 256;
            W2s[e] = W2[(size_t)kb * N_CLASS + e];
        }
        __syncthreads();

#pragma unroll 4
        for (int k = 0; k < 64; k++) {
            float a = As[row][k];
#pragma unroll
            for (int j = 0; j < 10; j++)
                acc[j] += a * W2s[k * N_CLASS + q * 10 + j];
        }
        __syncthreads();
    }

    int gm = bm + row;
    if (gm < N_NODES) {
#pragma unroll
        for (int j = 0; j < 10; j++)
            g_xs[(size_t)gm * N_CLASS + q * 10 + j] = acc[j] + b2[q * 10 + j];
    }
}

// ---------------- CSR build ----------------
__global__ void zero_count_kernel() {
    int i = blockIdx.x * blockDim.x + threadIdx.x;
    if (i < N_NODES) g_count[i] = 0;
}

__global__ void hist_kernel(const int* __restrict__ edge_row) {
    int e = blockIdx.x * blockDim.x + threadIdx.x;
    if (e < N_EDGES) atomicAdd(&g_count[edge_row[e]], 1);
}

// single-block exclusive scan -> g_rowptr, and cursor init
__global__ void scan_kernel() {
    __shared__ int warp_sums[32];
    __shared__ int carry_s;
    const int tid = threadIdx.x, lane = tid & 31, wid = tid >> 5;
    if (tid == 0) { carry_s = 0; g_rowptr[0] = 0; }
    __syncthreads();

    for (int base = 0; base < N_NODES; base += 1024) {
        int i = base + tid;
        int v = (i < N_NODES) ? g_count[i] : 0;
        int x = v;
#pragma unroll
        for (int off = 1; off < 32; off <<= 1) {
            int y = __shfl_up_sync(0xffffffffu, x, off);
            if (lane >= off) x += y;
        }
        if (lane == 31) warp_sums[wid] = x;
        __syncthreads();
        if (wid == 0) {
            int s = warp_sums[lane];
#pragma unroll
            for (int off = 1; off < 32; off <<= 1) {
                int y = __shfl_up_sync(0xffffffffu, s, off);
                if (lane >= off) s += y;
            }
            warp_sums[lane] = s;
        }
        __syncthreads();
        int incl = x + ((wid > 0) ? warp_sums[wid - 1] : 0) + carry_s;
        if (i < N_NODES) {
            g_rowptr[i + 1] = incl;
            g_cursor[i]     = incl - v;   // exclusive prefix
        }
        __syncthreads();
        if (tid == 1023) carry_s = incl;
        __syncthreads();
    }
}

__global__ void scatter_kernel(const int* __restrict__ edge_row,
                               const int* __restrict__ edge_col,
                               const float* __restrict__ edge_w) {
    int e = blockIdx.x * blockDim.x + threadIdx.x;
    if (e < N_EDGES) {
        int r = edge_row[e];
        int p = atomicAdd(&g_cursor[r], 1);
        g_cols[p]    = edge_col[e];
        g_wsorted[p] = edge_w[e];
    }
}

// ---------------- SpMM hop: xs[hop] = A_sparse @ xs[hop-1] ----------------
// 10 threads per row, each owns a float4 (4 channels) of the 40-channel row.
__global__ void spmm_kernel(int hop) {
    const float* __restrict__ xin  = g_xs + (size_t)(hop - 1) * N_NODES * N_CLASS;
    float* __restrict__       xout = g_xs + (size_t)hop * N_NODES * N_CLASS;

    int t    = blockIdx.x * blockDim.x + threadIdx.x;
    int row  = t / 10;
    int lane = t - row * 10;
    if (row >= N_NODES) return;

    int s = g_rowptr[row];
    int e = g_rowptr[row + 1];
    float4 acc = make_float4(0.f, 0.f, 0.f, 0.f);
    for (int i = s; i < e; i++) {
        int   c = g_cols[i];
        float w = g_wsorted[i];
        float4 v = *(const float4*)(xin + (size_t)c * N_CLASS + lane * 4);
        acc.x += w * v.x;
        acc.y += w * v.y;
        acc.z += w * v.z;
        acc.w += w * v.w;
    }
    *(float4*)(xout + (size_t)row * N_CLASS + lane * 4) = acc;
}

// ---------------- attention + log_softmax, one warp per node ----------------
__global__ void attn_kernel(const float* __restrict__ Wa,
                            const float* __restrict__ ba,
                            float* __restrict__ out) {
    int gwarp = (blockIdx.x * blockDim.x + threadIdx.x) >> 5;
    int lane  = threadIdx.x & 31;
    if (gwarp >= N_NODES) return;
    const int n = gwarp;

    const float wa0 = Wa[lane];
    const float wa1 = (lane < 8) ? Wa[lane + 32] : 0.f;
    const float bav = ba[0];

    float acc0 = 0.f, acc1 = 0.f;
#pragma unroll
    for (int k = 0; k <= K_HOPS; k++) {
        const float* p = g_xs + ((size_t)k * N_NODES + n) * N_CLASS;
        float v0 = p[lane];
        float v1 = (lane < 8) ? p[lane + 32] : 0.f;
        float dot = v0 * wa0 + v1 * wa1;
#pragma unroll
        for (int off = 16; off > 0; off >>= 1)
            dot += __shfl_xor_sync(0xffffffffu, dot, off);
        float s = 1.f / (1.f + expf(-(dot + bav)));
        acc0 += s * v0;
        acc1 += s * v1;
    }

    // log_softmax over 40 values (acc0 on lanes 0..31, acc1 on lanes 0..7)
    float m = acc0;
    if (lane < 8) m = fmaxf(m, acc1);
#pragma unroll
    for (int off = 16; off > 0; off >>= 1)
        m = fmaxf(m, __shfl_xor_sync(0xffffffffu, m, off));

    float se = expf(acc0 - m) + ((lane < 8) ? expf(acc1 - m) : 0.f);
#pragma unroll
    for (int off = 16; off > 0; off >>= 1)
        se += __shfl_xor_sync(0xffffffffu, se, off);

    float lse = logf(se);
    out[(size_t)n * N_CLASS + lane] = acc0 - m - lse;
    if (lane < 8)
        out[(size_t)n * N_CLASS + lane + 32] = acc1 - m - lse;
}

// ---------------- launch ----------------
extern "C" void kernel_launch(void* const* d_in, const int* in_sizes, int n_in,
                              void* d_out, int out_size) {
    const float* feature  = (const float*)d_in[0];
    const int*   edge_row = (const int*)  d_in[1];
    const int*   edge_col = (const int*)  d_in[2];
    const float* edge_w   = (const float*)d_in[3];
    const float* W1       = (const float*)d_in[4];
    const float* b1       = (const float*)d_in[5];
    const float* W2       = (const float*)d_in[6];
    const float* b2       = (const float*)d_in[7];
    const float* Wa       = (const float*)d_in[8];
    const float* ba       = (const float*)d_in[9];
    float*       out      = (float*)d_out;

    // CSR build interleaved with dense path (same stream, serialized deps ok)
    zero_count_kernel<<<(N_NODES + 255) / 256, 256>>>();
    hist_kernel<<<(N_EDGES + 255) / 256, 256>>>(edge_row);
    scan_kernel<<<1, 1024>>>();
    scatter_kernel<<<(N_EDGES + 255) / 256, 256>>>(edge_row, edge_col, edge_w);

    gemm1_kernel<<<dim3((N_NODES + 127) / 128, N_HID / 64), 256>>>(feature, W1, b1);
    gemm2_kernel<<<(N_NODES + 63) / 64, 256>>>(W2, b2);

    for (int k = 1; k <= K_HOPS; k++)
        spmm_kernel<<<(N_NODES * 10 + 319) / 320, 320>>>(k);

    attn_kernel<<<(N_NODES * 32 + 255) / 256, 256>>>(Wa, ba, out);
}

// round 3
// speedup vs baseline: 1.3913x; 1.3913x over previous
#include <cuda_runtime.h>
#include <cuda_bf16.h>
#include <math.h>
#include <stdint.h>

#define N_NODES 100000
#define N_EDGES 3200000
#define N_FEAT  512
#define N_HID   256
#define N_CLASS 40
#define K_HOPS  10

// tcgen05 only exists in the arch-accelerated target (sm_103a / sm_100a).
// The harness also runs a plain compute_103 ptxas pass, which rejects it.
#if defined(__CUDA_ARCH_FEAT_SM103_ALL) || defined(__CUDA_ARCH_FEAT_SM100_ALL)
#define USE_TCGEN05 1
#else
#define USE_TCGEN05 0
#endif

// ---------------- scratch (no cudaMalloc allowed) ----------------
__device__ float g_h1[(size_t)N_NODES * N_HID];                   // 102.4 MB
__device__ float g_xs[(size_t)(K_HOPS + 1) * N_NODES * N_CLASS];  // 176 MB
__device__ float g_w1t[(size_t)N_HID * N_FEAT];                   // W1^T, 512 KB
__device__ int   g_rowptr[N_NODES + 1];
__device__ int   g_count[N_NODES];
__device__ int   g_cursor[N_NODES];
__device__ int   g_cols[N_EDGES];
__device__ float g_wsorted[N_EDGES];

// ================= PTX helpers =================
__device__ __forceinline__ uint32_t smem_to_u32(const void* p) {
    uint32_t a;
    asm("{ .reg .u64 t; cvta.to.shared.u64 t, %1; cvt.u32.u64 %0, t; }"
        : "=r"(a) : "l"(p));
    return a;
}

#if USE_TCGEN05
__device__ __forceinline__ uint32_t elect_one_pred() {
    uint32_t p;
    asm volatile("{\n\t.reg .pred p;\n\telect.sync _|p, 0xFFFFFFFF;\n\t"
                 "selp.b32 %0, 1, 0, p;\n\t}" : "=r"(p));
    return p;
}

#define TCGEN05_ALLOC(smem_addr, nCols) \
    asm volatile("tcgen05.alloc.cta_group::1.sync.aligned.shared::cta.b32 [%0], %1;" \
                 :: "r"((uint32_t)(smem_addr)), "r"((uint32_t)(nCols)) : "memory")
#define TCGEN05_DEALLOC(tmem, nCols) \
    asm volatile("tcgen05.dealloc.cta_group::1.sync.aligned.b32 %0, %1;" \
                 :: "r"(tmem), "r"((uint32_t)(nCols)))
#define TCGEN05_RELINQUISH() \
    asm volatile("tcgen05.relinquish_alloc_permit.cta_group::1.sync.aligned;")
#define TCGEN05_COMMIT(mbar) \
    asm volatile("tcgen05.commit.cta_group::1.mbarrier::arrive::one.shared::cluster.b64 [%0];" \
                 :: "r"((uint32_t)(mbar)) : "memory")
#define TCGEN05_WAIT_LD() \
    asm volatile("tcgen05.wait::ld.sync.aligned;" ::: "memory")
#define TCGEN05_FENCE_AFTER() \
    asm volatile("tcgen05.fence::after_thread_sync;" ::: "memory")
#define TCGEN05_FENCE_BEFORE() \
    asm volatile("tcgen05.fence::before_thread_sync;" ::: "memory")
#define MBARRIER_INIT(mbar, cnt) \
    asm volatile("mbarrier.init.shared.b64 [%0], %1;" \
                 :: "r"((uint32_t)(mbar)), "r"((uint32_t)(cnt)) : "memory")
#define MBARRIER_INVAL(mbar) \
    asm volatile("mbarrier.inval.shared.b64 [%0];" :: "r"((uint32_t)(mbar)) : "memory")
#define FENCE_PROXY_ASYNC() \
    asm volatile("fence.proxy.async.shared::cta;" ::: "memory")

#define MBARRIER_WAIT_PARITY(mbar, parity) do { \
    uint32_t _m = (uint32_t)(mbar); \
    uint32_t _p = (uint32_t)(parity); \
    uint32_t _done; \
    asm volatile("{\n\t.reg .pred p;\n\t" \
        "mbarrier.try_wait.parity.acquire.cta.shared::cta.b64 p, [%1], %2;\n\t" \
        "selp.b32 %0, 1, 0, p;\n\t}" : "=r"(_done) : "r"(_m), "r"(_p) : "memory"); \
    if (!_done) { \
        asm volatile("{\n\t.reg .pred P1;\n\t" \
            "WL_%=:\n\t" \
            "mbarrier.try_wait.parity.acquire.cta.shared::cta.b64 P1, [%0], %1, 0x989680;\n\t" \
            "@P1 bra.uni WD_%=;\n\t" \
            "bra.uni WL_%=;\n\t" \
            "WD_%=:\n\t}" :: "r"(_m), "r"(_p) : "memory"); \
    } \
} while (0)

#define TCGEN05_LD_32X32B_X32(r, tmem_addr) \
    asm volatile( \
        "tcgen05.ld.sync.aligned.32x32b.x32.b32 " \
        "{%0, %1, %2, %3, %4, %5, %6, %7, " \
        " %8, %9, %10, %11, %12, %13, %14, %15, " \
        " %16, %17, %18, %19, %20, %21, %22, %23, " \
        " %24, %25, %26, %27, %28, %29, %30, %31}, [%32];" \
        : "=r"((r)[0]),  "=r"((r)[1]),  "=r"((r)[2]),  "=r"((r)[3]), \
          "=r"((r)[4]),  "=r"((r)[5]),  "=r"((r)[6]),  "=r"((r)[7]), \
          "=r"((r)[8]),  "=r"((r)[9]),  "=r"((r)[10]), "=r"((r)[11]), \
          "=r"((r)[12]), "=r"((r)[13]), "=r"((r)[14]), "=r"((r)[15]), \
          "=r"((r)[16]), "=r"((r)[17]), "=r"((r)[18]), "=r"((r)[19]), \
          "=r"((r)[20]), "=r"((r)[21]), "=r"((r)[22]), "=r"((r)[23]), \
          "=r"((r)[24]), "=r"((r)[25]), "=r"((r)[26]), "=r"((r)[27]), \
          "=r"((r)[28]), "=r"((r)[29]), "=r"((r)[30]), "=r"((r)[31]) \
        : "r"(tmem_addr))

// SW128 K-major descriptor: layout=2 (SW128), version=1, SBO=64, LBO=1
static constexpr uint64_t SMEM_DESC_BASE_SW128 =
    (uint64_t(2) << 61) | (uint64_t(1) << 46) | (uint64_t(64) << 32) | (uint64_t(1) << 16);
#define MAKE_SMEM_DESC(base_addr) \
    (SMEM_DESC_BASE_SW128 | ((uint64_t)((base_addr) >> 4) & 0x3FFF))

// tf32 SS MMA idesc: c=F32 (1<<4), a=TF32 (2<<7), b=TF32 (2<<10),
// N/8 at bits[17:23), M/16 at bits[24:29)
static constexpr uint32_t IDESC_TF32 =
    (1u << 4) | (2u << 7) | (2u << 10) | ((256u / 8u) << 17) | ((128u / 16u) << 24);

__device__ __forceinline__ void mma_tf32_ss(uint32_t d, uint64_t ad, uint64_t bd,
                                            uint32_t idesc, bool acc) {
    uint32_t en = acc ? 1u : 0u;
    asm volatile(
        "{\n\t.reg .pred p;\n\tsetp.ne.u32 p, %5, 0;\n\t"
        "tcgen05.mma.cta_group::1.kind::tf32 [%0], %1, %2, %3, {%4, %4, %4, %4}, p;\n\t}"
        :: "r"(d), "l"(ad), "l"(bd), "r"(idesc), "r"(0u), "r"(en)
        : "memory");
}

__device__ __forceinline__ float to_tf32(float x) {
    uint32_t r;
    asm("cvt.rna.tf32.f32 %0, %1;" : "=r"(r) : "f"(x));
    return __uint_as_float(r);
}
#endif  // USE_TCGEN05

#define SMEM_SWIZZLE_128B(off) ((off) ^ (((off) >> 3) & 0x70))

// ---------------- W1 transpose: g_w1t[n][k] = W1[k][n] ----------------
__global__ void transpose_w1_kernel(const float* __restrict__ W1) {
    __shared__ float t[32][33];
    int bk = blockIdx.x * 32;
    int bn = blockIdx.y * 32;
    int x = threadIdx.x, y = threadIdx.y;
#pragma unroll
    for (int i = 0; i < 32; i += 8)
        t[y + i][x] = W1[(size_t)(bk + y + i) * N_HID + bn + x];
    __syncthreads();
#pragma unroll
    for (int i = 0; i < 32; i += 8)
        g_w1t[(size_t)(bn + y + i) * N_FEAT + bk + x] = t[x][y + i];
}

// ---------------- GEMM1: relu(feature @ W1 + b1) -> g_h1 ----------------
// TC path: CTA tile M=128, N=256, K chunks of 32 floats, double-buffered SMEM.
// Fallback path (non-'a' JIT): SIMT 128x64 tiles looped over 4 n-blocks.
#define G1_CHUNK_K   32
#define G1_NCHUNKS   (N_FEAT / G1_CHUNK_K)      // 16
#define G1_A_BYTES   (128 * 128)
#define G1_B_BYTES   (256 * 128)
#define G1_OFF_A0    1024
#define G1_OFF_A1    (G1_OFF_A0 + G1_A_BYTES)
#define G1_OFF_B0    (G1_OFF_A1 + G1_A_BYTES)
#define G1_OFF_B1    (G1_OFF_B0 + G1_B_BYTES)
#define G1_SMEM_TOTAL (G1_OFF_B1 + G1_B_BYTES)   // 99328

__global__ void __launch_bounds__(256) gemm1_tc_kernel(const float* __restrict__ A,
                                                       const float* __restrict__ bias) {
    extern __shared__ char smem[];
#if USE_TCGEN05
    const uint32_t sb = smem_to_u32(smem);
    const int tid  = threadIdx.x;
    const int wid  = tid >> 5;
    const int lane = tid & 31;
    const int bm   = blockIdx.x * 128;

    if (wid == 4) TCGEN05_ALLOC(sb + 0, 256);
    if (tid == 0) { MBARRIER_INIT(sb + 8, 1); MBARRIER_INIT(sb + 16, 1); }
    __syncthreads();
    uint32_t tmem;
    asm volatile("ld.shared.b32 %0, [%1];" : "=r"(tmem) : "r"(sb + 0));

    const uint32_t aoff[2] = {G1_OFF_A0, G1_OFF_A1};
    const uint32_t boff[2] = {G1_OFF_B0, G1_OFF_B1};

    for (int c = 0; c < G1_NCHUNKS; c++) {
        const int buf = c & 1;
        if (c >= 2) MBARRIER_WAIT_PARITY(sb + 8 + 8 * buf, ((c - 2) >> 1) & 1);

        // A chunk: 128 rows x 8 float4 (k = c*32 .. c*32+31), SW128-swizzled
#pragma unroll
        for (int r = 0; r < 4; r++) {
            int i   = tid + r * 256;
            int row = i >> 3;
            int f4  = i & 7;
            int gm  = bm + row;
            float4 v = make_float4(0.f, 0.f, 0.f, 0.f);
            if (gm < N_NODES)
                v = *(const float4*)(A + (size_t)gm * N_FEAT + c * G1_CHUNK_K + f4 * 4);
            v.x = to_tf32(v.x); v.y = to_tf32(v.y); v.z = to_tf32(v.z); v.w = to_tf32(v.w);
            uint32_t off = SMEM_SWIZZLE_128B((uint32_t)(row * 128 + f4 * 16));
            *(float4*)(smem + aoff[buf] + off) = v;
        }
        // B chunk: 256 n-rows x 8 float4 from W1^T
#pragma unroll
        for (int r = 0; r < 8; r++) {
            int i  = tid + r * 256;
            int n  = i >> 3;
            int f4 = i & 7;
            float4 v = *(const float4*)(g_w1t + (size_t)n * N_FEAT + c * G1_CHUNK_K + f4 * 4);
            v.x = to_tf32(v.x); v.y = to_tf32(v.y); v.z = to_tf32(v.z); v.w = to_tf32(v.w);
            uint32_t off = SMEM_SWIZZLE_128B((uint32_t)(n * 128 + f4 * 16));
            *(float4*)(smem + boff[buf] + off) = v;
        }
        FENCE_PROXY_ASYNC();
        __syncthreads();

        if (wid == 4) {
            if (elect_one_pred()) {
                uint64_t ad = MAKE_SMEM_DESC(sb + aoff[buf]);
                uint64_t bd = MAKE_SMEM_DESC(sb + boff[buf]);
#pragma unroll
                for (int ks = 0; ks < 4; ks++)
                    mma_tf32_ss(tmem, ad + ks * 2, bd + ks * 2, IDESC_TF32,
                                (c > 0) || (ks > 0));
                TCGEN05_COMMIT(sb + 8 + 8 * buf);
            }
        }
    }

    MBARRIER_WAIT_PARITY(sb + 8, 1);
    MBARRIER_WAIT_PARITY(sb + 16, 1);
    TCGEN05_FENCE_AFTER();

    // Epilogue: warps 0-3 read D (128 lanes x 256 cols fp32), bias+relu, store.
    if (wid < 4) {
        const int m = bm + wid * 32 + lane;
#pragma unroll
        for (int b = 0; b < 4; b++) {
            uint32_t r[64];
            TCGEN05_LD_32X32B_X32(r, tmem + b * 64);
            TCGEN05_LD_32X32B_X32(r + 32, tmem + b * 64 + 32);
            TCGEN05_WAIT_LD();
            if (m < N_NODES) {
                float* outp = g_h1 + (size_t)m * N_HID + b * 64;
#pragma unroll
                for (int j = 0; j < 64; j += 4) {
                    float4 o;
                    o.x = fmaxf(__uint_as_float(r[j + 0]) + bias[b * 64 + j + 0], 0.f);
                    o.y = fmaxf(__uint_as_float(r[j + 1]) + bias[b * 64 + j + 1], 0.f);
                    o.z = fmaxf(__uint_as_float(r[j + 2]) + bias[b * 64 + j + 2], 0.f);
                    o.w = fmaxf(__uint_as_float(r[j + 3]) + bias[b * 64 + j + 3], 0.f);
                    *(float4*)(outp + j) = o;
                }
            }
        }
        TCGEN05_FENCE_BEFORE();
    }
    __syncthreads();
    if (tid == 0) { MBARRIER_INVAL(sb + 8); MBARRIER_INVAL(sb + 16); }
    __syncthreads();
    if (wid == 4) { TCGEN05_RELINQUISH(); TCGEN05_DEALLOC(tmem, 256); }

#else  // ---------- SIMT fallback (plain sm_103 JIT path) ----------
    float (*As)[132] = (float(*)[132])smem;                       // [16][132]
    float (*Bs)[68]  = (float(*)[68])(smem + 16 * 132 * sizeof(float));

    const int tid  = threadIdx.x;
    const int bm   = blockIdx.x * 128;
    const int mIdx = tid >> 4;
    const int nIdx = tid & 15;

    for (int nb = 0; nb < 4; nb++) {
        const int bn = nb * 64;
        float acc[8][4];
#pragma unroll
        for (int i = 0; i < 8; i++)
#pragma unroll
            for (int j = 0; j < 4; j++) acc[i][j] = 0.f;

        for (int kt = 0; kt < N_FEAT; kt += 16) {
#pragma unroll
            for (int r = 0; r < 2; r++) {
                int i  = tid + r * 256;
                int m  = i >> 2;
                int k4 = (i & 3) * 4;
                int gm = bm + m;
                float4 v = make_float4(0.f, 0.f, 0.f, 0.f);
                if (gm < N_NODES)
                    v = *(const float4*)(A + (size_t)gm * N_FEAT + kt + k4);
                As[k4 + 0][m] = v.x;
                As[k4 + 1][m] = v.y;
                As[k4 + 2][m] = v.z;
                As[k4 + 3][m] = v.w;
            }
            {
                int n  = tid >> 2;
                int k4 = (tid & 3) * 4;
                float4 v = *(const float4*)(g_w1t + (size_t)(bn + n) * N_FEAT + kt + k4);
                Bs[k4 + 0][n] = v.x;
                Bs[k4 + 1][n] = v.y;
                Bs[k4 + 2][n] = v.z;
                Bs[k4 + 3][n] = v.w;
            }
            __syncthreads();

#pragma unroll
            for (int k = 0; k < 16; k++) {
                float ra[8], rb[4];
#pragma unroll
                for (int i = 0; i < 8; i++) ra[i] = As[k][mIdx * 8 + i];
#pragma unroll
                for (int j = 0; j < 4; j++) rb[j] = Bs[k][nIdx * 4 + j];
#pragma unroll
                for (int i = 0; i < 8; i++)
#pragma unroll
                    for (int j = 0; j < 4; j++) acc[i][j] += ra[i] * rb[j];
            }
            __syncthreads();
        }

#pragma unroll
        for (int i = 0; i < 8; i++) {
            int gm = bm + mIdx * 8 + i;
            if (gm < N_NODES) {
#pragma unroll
                for (int j = 0; j < 4; j++) {
                    int gn = bn + nIdx * 4 + j;
                    float v = acc[i][j] + bias[gn];
                    g_h1[(size_t)gm * N_HID + gn] = fmaxf(v, 0.f);
                }
            }
        }
    }
#endif
}

// ---------------- GEMM2: g_h1 @ W2 + b2 -> g_xs plane 0 ----------------
__global__ void gemm2_kernel(const float* __restrict__ W2,
                             const float* __restrict__ b2) {
    __shared__ float As[64][65];
    __shared__ float W2s[64 * N_CLASS];

    const int tid = threadIdx.x;
    const int bm  = blockIdx.x * 64;
    const int row = tid >> 2;
    const int q   = tid & 3;

    float acc[10];
#pragma unroll
    for (int j = 0; j < 10; j++) acc[j] = 0.f;

    for (int kb = 0; kb < N_HID; kb += 64) {
#pragma unroll
        for (int r = 0; r < 4; r++) {
            int i  = tid + r * 256;
            int rr = i >> 4;
            int c4 = (i & 15) * 4;
            int gm = bm + rr;
            float4 v = make_float4(0.f, 0.f, 0.f, 0.f);
            if (gm < N_NODES)
                v = *(const float4*)(g_h1 + (size_t)gm * N_HID + kb + c4);
            As[rr][c4 + 0] = v.x;
            As[rr][c4 + 1] = v.y;
            As[rr][c4 + 2] = v.z;
            As[rr][c4 + 3] = v.w;
        }
#pragma unroll
        for (int r = 0; r < 10; r++) {
            int e = tid + r * 256;
            W2s[e] = W2[(size_t)kb * N_CLASS + e];
        }
        __syncthreads();

#pragma unroll 4
        for (int k = 0; k < 64; k++) {
            float a = As[row][k];
#pragma unroll
            for (int j = 0; j < 10; j++)
                acc[j] += a * W2s[k * N_CLASS + q * 10 + j];
        }
        __syncthreads();
    }

    int gm = bm + row;
    if (gm < N_NODES) {
#pragma unroll
        for (int j = 0; j < 10; j++)
            g_xs[(size_t)gm * N_CLASS + q * 10 + j] = acc[j] + b2[q * 10 + j];
    }
}

// ---------------- CSR build ----------------
__global__ void zero_count_kernel() {
    int i = blockIdx.x * blockDim.x + threadIdx.x;
    if (i < N_NODES) g_count[i] = 0;
}

__global__ void hist_kernel(const int* __restrict__ edge_row) {
    int e = blockIdx.x * blockDim.x + threadIdx.x;
    if (e < N_EDGES) atomicAdd(&g_count[edge_row[e]], 1);
}

__global__ void scan_kernel() {
    __shared__ int warp_sums[32];
    __shared__ int carry_s;
    const int tid = threadIdx.x, lane = tid & 31, wid = tid >> 5;
    if (tid == 0) { carry_s = 0; g_rowptr[0] = 0; }
    __syncthreads();

    for (int base = 0; base < N_NODES; base += 1024) {
        int i = base + tid;
        int v = (i < N_NODES) ? g_count[i] : 0;
        int x = v;
#pragma unroll
        for (int off = 1; off < 32; off <<= 1) {
            int y = __shfl_up_sync(0xffffffffu, x, off);
            if (lane >= off) x += y;
        }
        if (lane == 31) warp_sums[wid] = x;
        __syncthreads();
        if (wid == 0) {
            int s = warp_sums[lane];
#pragma unroll
            for (int off = 1; off < 32; off <<= 1) {
                int y = __shfl_up_sync(0xffffffffu, s, off);
                if (lane >= off) s += y;
            }
            warp_sums[lane] = s;
        }
        __syncthreads();
        int incl = x + ((wid > 0) ? warp_sums[wid - 1] : 0) + carry_s;
        if (i < N_NODES) {
            g_rowptr[i + 1] = incl;
            g_cursor[i]     = incl - v;
        }
        __syncthreads();
        if (tid == 1023) carry_s = incl;
        __syncthreads();
    }
}

__global__ void scatter_kernel(const int* __restrict__ edge_row,
                               const int* __restrict__ edge_col,
                               const float* __restrict__ edge_w) {
    int e = blockIdx.x * blockDim.x + threadIdx.x;
    if (e < N_EDGES) {
        int r = edge_row[e];
        int p = atomicAdd(&g_cursor[r], 1);
        g_cols[p]    = edge_col[e];
        g_wsorted[p] = edge_w[e];
    }
}

// ---------------- SpMM hop ----------------
__global__ void spmm_kernel(int hop) {
    const float* __restrict__ xin  = g_xs + (size_t)(hop - 1) * N_NODES * N_CLASS;
    float* __restrict__       xout = g_xs + (size_t)hop * N_NODES * N_CLASS;

    int t    = blockIdx.x * blockDim.x + threadIdx.x;
    int row  = t / 10;
    int lane = t - row * 10;
    if (row >= N_NODES) return;

    int s = g_rowptr[row];
    int e = g_rowptr[row + 1];
    float4 acc = make_float4(0.f, 0.f, 0.f, 0.f);
    for (int i = s; i < e; i++) {
        int   c = g_cols[i];
        float w = g_wsorted[i];
        float4 v = *(const float4*)(xin + (size_t)c * N_CLASS + lane * 4);
        acc.x += w * v.x;
        acc.y += w * v.y;
        acc.z += w * v.z;
        acc.w += w * v.w;
    }
    *(float4*)(xout + (size_t)row * N_CLASS + lane * 4) = acc;
}

// ---------------- attention + log_softmax ----------------
__global__ void attn_kernel(const float* __restrict__ Wa,
                            const float* __restrict__ ba,
                            float* __restrict__ out) {
    int gwarp = (blockIdx.x * blockDim.x + threadIdx.x) >> 5;
    int lane  = threadIdx.x & 31;
    if (gwarp >= N_NODES) return;
    const int n = gwarp;

    const float wa0 = Wa[lane];
    const float wa1 = (lane < 8) ? Wa[lane + 32] : 0.f;
    const float bav = ba[0];

    float acc0 = 0.f, acc1 = 0.f;
#pragma unroll
    for (int k = 0; k <= K_HOPS; k++) {
        const float* p = g_xs + ((size_t)k * N_NODES + n) * N_CLASS;
        float v0 = p[lane];
        float v1 = (lane < 8) ? p[lane + 32] : 0.f;
        float dot = v0 * wa0 + v1 * wa1;
#pragma unroll
        for (int off = 16; off > 0; off >>= 1)
            dot += __shfl_xor_sync(0xffffffffu, dot, off);
        float s = 1.f / (1.f + expf(-(dot + bav)));
        acc0 += s * v0;
        acc1 += s * v1;
    }

    float m = acc0;
    if (lane < 8) m = fmaxf(m, acc1);
#pragma unroll
    for (int off = 16; off > 0; off >>= 1)
        m = fmaxf(m, __shfl_xor_sync(0xffffffffu, m, off));

    float se = expf(acc0 - m) + ((lane < 8) ? expf(acc1 - m) : 0.f);
#pragma unroll
    for (int off = 16; off > 0; off >>= 1)
        se += __shfl_xor_sync(0xffffffffu, se, off);

    float lse = logf(se);
    out[(size_t)n * N_CLASS + lane] = acc0 - m - lse;
    if (lane < 8)
        out[(size_t)n * N_CLASS + lane + 32] = acc1 - m - lse;
}

// ---------------- launch ----------------
extern "C" void kernel_launch(void* const* d_in, const int* in_sizes, int n_in,
                              void* d_out, int out_size) {
    const float* feature  = (const float*)d_in[0];
    const int*   edge_row = (const int*)  d_in[1];
    const int*   edge_col = (const int*)  d_in[2];
    const float* edge_w   = (const float*)d_in[3];
    const float* W1       = (const float*)d_in[4];
    const float* b1       = (const float*)d_in[5];
    const float* W2       = (const float*)d_in[6];
    const float* b2       = (const float*)d_in[7];
    const float* Wa       = (const float*)d_in[8];
    const float* ba       = (const float*)d_in[9];
    float*       out      = (float*)d_out;

    cudaFuncSetAttribute(gemm1_tc_kernel,
                         cudaFuncAttributeMaxDynamicSharedMemorySize, G1_SMEM_TOTAL);

    // CSR build
    zero_count_kernel<<<(N_NODES + 255) / 256, 256>>>();
    hist_kernel<<<(N_EDGES + 255) / 256, 256>>>(edge_row);
    scan_kernel<<<1, 1024>>>();
    scatter_kernel<<<(N_EDGES + 255) / 256, 256>>>(edge_row, edge_col, edge_w);

    // Dense path
    transpose_w1_kernel<<<dim3(N_FEAT / 32, N_HID / 32), dim3(32, 8)>>>(W1);
    gemm1_tc_kernel<<<(N_NODES + 127) / 128, 256, G1_SMEM_TOTAL>>>(feature, b1);
    gemm2_kernel<<<(N_NODES + 63) / 64, 256>>>(W2, b2);

    for (int k = 1; k <= K_HOPS; k++)
        spmm_kernel<<<(N_NODES * 10 + 319) / 320, 320>>>(k);

    attn_kernel<<<(N_NODES * 32 + 255) / 256, 256>>>(Wa, ba, out);
}

// round 4
// speedup vs baseline: 1.4995x; 1.0778x over previous
#include <cuda_runtime.h>
#include <cuda_bf16.h>
#include <math.h>
#include <stdint.h>

#define N_NODES 100000
#define N_EDGES 3200000
#define N_FEAT  512
#define N_HID   256
#define N_CLASS 40
#define K_HOPS  10

// tcgen05 only exists in the arch-accelerated target (sm_103a / sm_100a).
// The harness also runs a plain compute_103 ptxas pass, which rejects it.
#if defined(__CUDA_ARCH_FEAT_SM103_ALL) || defined(__CUDA_ARCH_FEAT_SM100_ALL)
#define USE_TCGEN05 1
#else
#define USE_TCGEN05 0
#endif

// ---------------- scratch (no cudaMalloc allowed) ----------------
__device__ float g_h1[(size_t)N_NODES * N_HID];                   // 102.4 MB
__device__ float g_xs[(size_t)(K_HOPS + 1) * N_NODES * N_CLASS];  // 176 MB
__device__ float g_w1t[(size_t)N_HID * N_FEAT];                   // W1^T, 512 KB
__device__ int   g_rowptr[N_NODES + 1];
__device__ int   g_count[N_NODES];
__device__ int   g_cursor[N_NODES];
__device__ int   g_cols[N_EDGES];
__device__ float g_wsorted[N_EDGES];

// ================= PTX helpers =================
__device__ __forceinline__ uint32_t smem_to_u32(const void* p) {
    uint32_t a;
    asm("{ .reg .u64 t; cvta.to.shared.u64 t, %1; cvt.u32.u64 %0, t; }"
        : "=r"(a) : "l"(p));
    return a;
}

#if USE_TCGEN05
__device__ __forceinline__ uint32_t elect_one_pred() {
    uint32_t p;
    asm volatile("{\n\t.reg .pred p;\n\telect.sync _|p, 0xFFFFFFFF;\n\t"
                 "selp.b32 %0, 1, 0, p;\n\t}" : "=r"(p));
    return p;
}

#define TCGEN05_ALLOC(smem_addr, nCols) \
    asm volatile("tcgen05.alloc.cta_group::1.sync.aligned.shared::cta.b32 [%0], %1;" \
                 :: "r"((uint32_t)(smem_addr)), "r"((uint32_t)(nCols)) : "memory")
#define TCGEN05_DEALLOC(tmem, nCols) \
    asm volatile("tcgen05.dealloc.cta_group::1.sync.aligned.b32 %0, %1;" \
                 :: "r"(tmem), "r"((uint32_t)(nCols)))
#define TCGEN05_RELINQUISH() \
    asm volatile("tcgen05.relinquish_alloc_permit.cta_group::1.sync.aligned;")
#define TCGEN05_COMMIT(mbar) \
    asm volatile("tcgen05.commit.cta_group::1.mbarrier::arrive::one.shared::cluster.b64 [%0];" \
                 :: "r"((uint32_t)(mbar)) : "memory")
#define TCGEN05_WAIT_LD() \
    asm volatile("tcgen05.wait::ld.sync.aligned;" ::: "memory")
#define TCGEN05_FENCE_AFTER() \
    asm volatile("tcgen05.fence::after_thread_sync;" ::: "memory")
#define TCGEN05_FENCE_BEFORE() \
    asm volatile("tcgen05.fence::before_thread_sync;" ::: "memory")
#define MBARRIER_INIT(mbar, cnt) \
    asm volatile("mbarrier.init.shared.b64 [%0], %1;" \
                 :: "r"((uint32_t)(mbar)), "r"((uint32_t)(cnt)) : "memory")
#define MBARRIER_INVAL(mbar) \
    asm volatile("mbarrier.inval.shared.b64 [%0];" :: "r"((uint32_t)(mbar)) : "memory")
#define FENCE_PROXY_ASYNC() \
    asm volatile("fence.proxy.async.shared::cta;" ::: "memory")

#define MBARRIER_WAIT_PARITY(mbar, parity) do { \
    uint32_t _m = (uint32_t)(mbar); \
    uint32_t _p = (uint32_t)(parity); \
    uint32_t _done; \
    asm volatile("{\n\t.reg .pred p;\n\t" \
        "mbarrier.try_wait.parity.acquire.cta.shared::cta.b64 p, [%1], %2;\n\t" \
        "selp.b32 %0, 1, 0, p;\n\t}" : "=r"(_done) : "r"(_m), "r"(_p) : "memory"); \
    if (!_done) { \
        asm volatile("{\n\t.reg .pred P1;\n\t" \
            "WL_%=:\n\t" \
            "mbarrier.try_wait.parity.acquire.cta.shared::cta.b64 P1, [%0], %1, 0x989680;\n\t" \
            "@P1 bra.uni WD_%=;\n\t" \
            "bra.uni WL_%=;\n\t" \
            "WD_%=:\n\t}" :: "r"(_m), "r"(_p) : "memory"); \
    } \
} while (0)

#define TCGEN05_LD_32X32B_X32(r, tmem_addr) \
    asm volatile( \
        "tcgen05.ld.sync.aligned.32x32b.x32.b32 " \
        "{%0, %1, %2, %3, %4, %5, %6, %7, " \
        " %8, %9, %10, %11, %12, %13, %14, %15, " \
        " %16, %17, %18, %19, %20, %21, %22, %23, " \
        " %24, %25, %26, %27, %28, %29, %30, %31}, [%32];" \
        : "=r"((r)[0]),  "=r"((r)[1]),  "=r"((r)[2]),  "=r"((r)[3]), \
          "=r"((r)[4]),  "=r"((r)[5]),  "=r"((r)[6]),  "=r"((r)[7]), \
          "=r"((r)[8]),  "=r"((r)[9]),  "=r"((r)[10]), "=r"((r)[11]), \
          "=r"((r)[12]), "=r"((r)[13]), "=r"((r)[14]), "=r"((r)[15]), \
          "=r"((r)[16]), "=r"((r)[17]), "=r"((r)[18]), "=r"((r)[19]), \
          "=r"((r)[20]), "=r"((r)[21]), "=r"((r)[22]), "=r"((r)[23]), \
          "=r"((r)[24]), "=r"((r)[25]), "=r"((r)[26]), "=r"((r)[27]), \
          "=r"((r)[28]), "=r"((r)[29]), "=r"((r)[30]), "=r"((r)[31]) \
        : "r"(tmem_addr))

// SW128 K-major descriptor: layout=2 (SW128), version=1, SBO=64, LBO=1
static constexpr uint64_t SMEM_DESC_BASE_SW128 =
    (uint64_t(2) << 61) | (uint64_t(1) << 46) | (uint64_t(64) << 32) | (uint64_t(1) << 16);
#define MAKE_SMEM_DESC(base_addr) \
    (SMEM_DESC_BASE_SW128 | ((uint64_t)((base_addr) >> 4) & 0x3FFF))

// tf32 SS MMA idesc: c=F32 (1<<4), a=TF32 (2<<7), b=TF32 (2<<10),
// N/8 at bits[17:23), M/16 at bits[24:29)
static constexpr uint32_t IDESC_TF32 =
    (1u << 4) | (2u << 7) | (2u << 10) | ((256u / 8u) << 17) | ((128u / 16u) << 24);

__device__ __forceinline__ void mma_tf32_ss(uint32_t d, uint64_t ad, uint64_t bd,
                                            uint32_t idesc, bool acc) {
    uint32_t en = acc ? 1u : 0u;
    asm volatile(
        "{\n\t.reg .pred p;\n\tsetp.ne.u32 p, %5, 0;\n\t"
        "tcgen05.mma.cta_group::1.kind::tf32 [%0], %1, %2, %3, {%4, %4, %4, %4}, p;\n\t}"
        :: "r"(d), "l"(ad), "l"(bd), "r"(idesc), "r"(0u), "r"(en)
        : "memory");
}

__device__ __forceinline__ float to_tf32(float x) {
    uint32_t r;
    asm("cvt.rna.tf32.f32 %0, %1;" : "=r"(r) : "f"(x));
    return __uint_as_float(r);
}
#endif  // USE_TCGEN05

#define SMEM_SWIZZLE_128B(off) ((off) ^ (((off) >> 3) & 0x70))

// ---------------- W1 transpose: g_w1t[n][k] = W1[k][n] ----------------
__global__ void transpose_w1_kernel(const float* __restrict__ W1) {
    __shared__ float t[32][33];
    int bk = blockIdx.x * 32;
    int bn = blockIdx.y * 32;
    int x = threadIdx.x, y = threadIdx.y;
#pragma unroll
    for (int i = 0; i < 32; i += 8)
        t[y + i][x] = W1[(size_t)(bk + y + i) * N_HID + bn + x];
    __syncthreads();
#pragma unroll
    for (int i = 0; i < 32; i += 8)
        g_w1t[(size_t)(bn + y + i) * N_FEAT + bk + x] = t[x][y + i];
}

// ---------------- GEMM1: relu(feature @ W1 + b1) -> g_h1 ----------------
#define G1_CHUNK_K   32
#define G1_NCHUNKS   (N_FEAT / G1_CHUNK_K)      // 16
#define G1_A_BYTES   (128 * 128)
#define G1_B_BYTES   (256 * 128)
#define G1_OFF_A0    1024
#define G1_OFF_A1    (G1_OFF_A0 + G1_A_BYTES)
#define G1_OFF_B0    (G1_OFF_A1 + G1_A_BYTES)
#define G1_OFF_B1    (G1_OFF_B0 + G1_B_BYTES)
#define G1_SMEM_TOTAL (G1_OFF_B1 + G1_B_BYTES)   // 99328

__global__ void __launch_bounds__(256) gemm1_tc_kernel(const float* __restrict__ A,
                                                       const float* __restrict__ bias) {
    extern __shared__ char smem[];
#if USE_TCGEN05
    const uint32_t sb = smem_to_u32(smem);
    const int tid  = threadIdx.x;
    const int wid  = tid >> 5;
    const int lane = tid & 31;
    const int bm   = blockIdx.x * 128;

    if (wid == 4) TCGEN05_ALLOC(sb + 0, 256);
    if (tid == 0) { MBARRIER_INIT(sb + 8, 1); MBARRIER_INIT(sb + 16, 1); }
    __syncthreads();
    uint32_t tmem;
    asm volatile("ld.shared.b32 %0, [%1];" : "=r"(tmem) : "r"(sb + 0));

    const uint32_t aoff[2] = {G1_OFF_A0, G1_OFF_A1};
    const uint32_t boff[2] = {G1_OFF_B0, G1_OFF_B1};

    for (int c = 0; c < G1_NCHUNKS; c++) {
        const int buf = c & 1;
        if (c >= 2) MBARRIER_WAIT_PARITY(sb + 8 + 8 * buf, ((c - 2) >> 1) & 1);

        // A chunk: 128 rows x 8 float4 (k = c*32 .. c*32+31), SW128-swizzled
#pragma unroll
        for (int r = 0; r < 4; r++) {
            int i   = tid + r * 256;
            int row = i >> 3;
            int f4  = i & 7;
            int gm  = bm + row;
            float4 v = make_float4(0.f, 0.f, 0.f, 0.f);
            if (gm < N_NODES)
                v = *(const float4*)(A + (size_t)gm * N_FEAT + c * G1_CHUNK_K + f4 * 4);
            v.x = to_tf32(v.x); v.y = to_tf32(v.y); v.z = to_tf32(v.z); v.w = to_tf32(v.w);
            uint32_t off = SMEM_SWIZZLE_128B((uint32_t)(row * 128 + f4 * 16));
            *(float4*)(smem + aoff[buf] + off) = v;
        }
        // B chunk: 256 n-rows x 8 float4 from W1^T
#pragma unroll
        for (int r = 0; r < 8; r++) {
            int i  = tid + r * 256;
            int n  = i >> 3;
            int f4 = i & 7;
            float4 v = *(const float4*)(g_w1t + (size_t)n * N_FEAT + c * G1_CHUNK_K + f4 * 4);
            v.x = to_tf32(v.x); v.y = to_tf32(v.y); v.z = to_tf32(v.z); v.w = to_tf32(v.w);
            uint32_t off = SMEM_SWIZZLE_128B((uint32_t)(n * 128 + f4 * 16));
            *(float4*)(smem + boff[buf] + off) = v;
        }
        FENCE_PROXY_ASYNC();
        __syncthreads();

        if (wid == 4) {
            if (elect_one_pred()) {
                uint64_t ad = MAKE_SMEM_DESC(sb + aoff[buf]);
                uint64_t bd = MAKE_SMEM_DESC(sb + boff[buf]);
#pragma unroll
                for (int ks = 0; ks < 4; ks++)
                    mma_tf32_ss(tmem, ad + ks * 2, bd + ks * 2, IDESC_TF32,
                                (c > 0) || (ks > 0));
                TCGEN05_COMMIT(sb + 8 + 8 * buf);
            }
        }
    }

    MBARRIER_WAIT_PARITY(sb + 8, 1);
    MBARRIER_WAIT_PARITY(sb + 16, 1);
    TCGEN05_FENCE_AFTER();

    // Epilogue: warps 0-3 read D (128 lanes x 256 cols fp32), bias+relu, store.
    if (wid < 4) {
        const int m = bm + wid * 32 + lane;
#pragma unroll
        for (int b = 0; b < 4; b++) {
            uint32_t r[64];
            TCGEN05_LD_32X32B_X32(r, tmem + b * 64);
            TCGEN05_LD_32X32B_X32(r + 32, tmem + b * 64 + 32);
            TCGEN05_WAIT_LD();
            if (m < N_NODES) {
                float* outp = g_h1 + (size_t)m * N_HID + b * 64;
#pragma unroll
                for (int j = 0; j < 64; j += 4) {
                    float4 o;
                    o.x = fmaxf(__uint_as_float(r[j + 0]) + bias[b * 64 + j + 0], 0.f);
                    o.y = fmaxf(__uint_as_float(r[j + 1]) + bias[b * 64 + j + 1], 0.f);
                    o.z = fmaxf(__uint_as_float(r[j + 2]) + bias[b * 64 + j + 2], 0.f);
                    o.w = fmaxf(__uint_as_float(r[j + 3]) + bias[b * 64 + j + 3], 0.f);
                    *(float4*)(outp + j) = o;
                }
            }
        }
        TCGEN05_FENCE_BEFORE();
    }
    __syncthreads();
    if (tid == 0) { MBARRIER_INVAL(sb + 8); MBARRIER_INVAL(sb + 16); }
    __syncthreads();
    if (wid == 4) { TCGEN05_RELINQUISH(); TCGEN05_DEALLOC(tmem, 256); }

#else  // ---------- SIMT fallback (plain sm_103 JIT path) ----------
    float (*As)[132] = (float(*)[132])smem;
    float (*Bs)[68]  = (float(*)[68])(smem + 16 * 132 * sizeof(float));

    const int tid  = threadIdx.x;
    const int bm   = blockIdx.x * 128;
    const int mIdx = tid >> 4;
    const int nIdx = tid & 15;

    for (int nb = 0; nb < 4; nb++) {
        const int bn = nb * 64;
        float acc[8][4];
#pragma unroll
        for (int i = 0; i < 8; i++)
#pragma unroll
            for (int j = 0; j < 4; j++) acc[i][j] = 0.f;

        for (int kt = 0; kt < N_FEAT; kt += 16) {
#pragma unroll
            for (int r = 0; r < 2; r++) {
                int i  = tid + r * 256;
                int m  = i >> 2;
                int k4 = (i & 3) * 4;
                int gm = bm + m;
                float4 v = make_float4(0.f, 0.f, 0.f, 0.f);
                if (gm < N_NODES)
                    v = *(const float4*)(A + (size_t)gm * N_FEAT + kt + k4);
                As[k4 + 0][m] = v.x;
                As[k4 + 1][m] = v.y;
                As[k4 + 2][m] = v.z;
                As[k4 + 3][m] = v.w;
            }
            {
                int n  = tid >> 2;
                int k4 = (tid & 3) * 4;
                float4 v = *(const float4*)(g_w1t + (size_t)(bn + n) * N_FEAT + kt + k4);
                Bs[k4 + 0][n] = v.x;
                Bs[k4 + 1][n] = v.y;
                Bs[k4 + 2][n] = v.z;
                Bs[k4 + 3][n] = v.w;
            }
            __syncthreads();

#pragma unroll
            for (int k = 0; k < 16; k++) {
                float ra[8], rb[4];
#pragma unroll
                for (int i = 0; i < 8; i++) ra[i] = As[k][mIdx * 8 + i];
#pragma unroll
                for (int j = 0; j < 4; j++) rb[j] = Bs[k][nIdx * 4 + j];
#pragma unroll
                for (int i = 0; i < 8; i++)
#pragma unroll
                    for (int j = 0; j < 4; j++) acc[i][j] += ra[i] * rb[j];
            }
            __syncthreads();
        }

#pragma unroll
        for (int i = 0; i < 8; i++) {
            int gm = bm + mIdx * 8 + i;
            if (gm < N_NODES) {
#pragma unroll
                for (int j = 0; j < 4; j++) {
                    int gn = bn + nIdx * 4 + j;
                    float v = acc[i][j] + bias[gn];
                    g_h1[(size_t)gm * N_HID + gn] = fmaxf(v, 0.f);
                }
            }
        }
    }
#endif
}

// ---------------- GEMM2: g_h1 @ W2 + b2 -> g_xs plane 0 ----------------
__global__ void gemm2_kernel(const float* __restrict__ W2,
                             const float* __restrict__ b2) {
    __shared__ float As[64][65];
    __shared__ float W2s[64 * N_CLASS];

    const int tid = threadIdx.x;
    const int bm  = blockIdx.x * 64;
    const int row = tid >> 2;
    const int q   = tid & 3;

    float acc[10];
#pragma unroll
    for (int j = 0; j < 10; j++) acc[j] = 0.f;

    for (int kb = 0; kb < N_HID; kb += 64) {
#pragma unroll
        for (int r = 0; r < 4; r++) {
            int i  = tid + r * 256;
            int rr = i >> 4;
            int c4 = (i & 15) * 4;
            int gm = bm + rr;
            float4 v = make_float4(0.f, 0.f, 0.f, 0.f);
            if (gm < N_NODES)
                v = *(const float4*)(g_h1 + (size_t)gm * N_HID + kb + c4);
            As[rr][c4 + 0] = v.x;
            As[rr][c4 + 1] = v.y;
            As[rr][c4 + 2] = v.z;
            As[rr][c4 + 3] = v.w;
        }
#pragma unroll
        for (int r = 0; r < 10; r++) {
            int e = tid + r * 256;
            W2s[e] = W2[(size_t)kb * N_CLASS + e];
        }
        __syncthreads();

#pragma unroll 4
        for (int k = 0; k < 64; k++) {
            float a = As[row][k];
#pragma unroll
            for (int j = 0; j < 10; j++)
                acc[j] += a * W2s[k * N_CLASS + q * 10 + j];
        }
        __syncthreads();
    }

    int gm = bm + row;
    if (gm < N_NODES) {
#pragma unroll
        for (int j = 0; j < 10; j++)
            g_xs[(size_t)gm * N_CLASS + q * 10 + j] = acc[j] + b2[q * 10 + j];
    }
}

// ---------------- CSR build ----------------
__global__ void zero_count_kernel() {
    int i = blockIdx.x * blockDim.x + threadIdx.x;
    if (i < N_NODES) g_count[i] = 0;
}

__global__ void hist_kernel(const int* __restrict__ edge_row) {
    int e = blockIdx.x * blockDim.x + threadIdx.x;
    if (e < N_EDGES) atomicAdd(&g_count[edge_row[e]], 1);
}

__global__ void scan_kernel() {
    __shared__ int warp_sums[32];
    __shared__ int carry_s;
    const int tid = threadIdx.x, lane = tid & 31, wid = tid >> 5;
    if (tid == 0) { carry_s = 0; g_rowptr[0] = 0; }
    __syncthreads();

    for (int base = 0; base < N_NODES; base += 1024) {
        int i = base + tid;
        int v = (i < N_NODES) ? g_count[i] : 0;
        int x = v;
#pragma unroll
        for (int off = 1; off < 32; off <<= 1) {
            int y = __shfl_up_sync(0xffffffffu, x, off);
            if (lane >= off) x += y;
        }
        if (lane == 31) warp_sums[wid] = x;
        __syncthreads();
        if (wid == 0) {
            int s = warp_sums[lane];
#pragma unroll
            for (int off = 1; off < 32; off <<= 1) {
                int y = __shfl_up_sync(0xffffffffu, s, off);
                if (lane >= off) s += y;
            }
            warp_sums[lane] = s;
        }
        __syncthreads();
        int incl = x + ((wid > 0) ? warp_sums[wid - 1] : 0) + carry_s;
        if (i < N_NODES) {
            g_rowptr[i + 1] = incl;
            g_cursor[i]     = incl - v;
        }
        __syncthreads();
        if (tid == 1023) carry_s = incl;
        __syncthreads();
    }
}

__global__ void scatter_kernel(const int* __restrict__ edge_row,
                               const int* __restrict__ edge_col,
                               const float* __restrict__ edge_w) {
    int e = blockIdx.x * blockDim.x + threadIdx.x;
    if (e < N_EDGES) {
        int r = edge_row[e];
        int p = atomicAdd(&g_cursor[r], 1);
        g_cols[p]    = edge_col[e];
        g_wsorted[p] = edge_w[e];
    }
}

// ---------------- SpMM hop ----------------
__global__ void spmm_kernel(int hop) {
    const float* __restrict__ xin  = g_xs + (size_t)(hop - 1) * N_NODES * N_CLASS;
    float* __restrict__       xout = g_xs + (size_t)hop * N_NODES * N_CLASS;

    int t    = blockIdx.x * blockDim.x + threadIdx.x;
    int row  = t / 10;
    int lane = t - row * 10;
    if (row >= N_NODES) return;

    int s = g_rowptr[row];
    int e = g_rowptr[row + 1];
    float4 acc = make_float4(0.f, 0.f, 0.f, 0.f);
    for (int i = s; i < e; i++) {
        int   c = g_cols[i];
        float w = g_wsorted[i];
        float4 v = *(const float4*)(xin + (size_t)c * N_CLASS + lane * 4);
        acc.x += w * v.x;
        acc.y += w * v.y;
        acc.z += w * v.z;
        acc.w += w * v.w;
    }
    *(float4*)(xout + (size_t)row * N_CLASS + lane * 4) = acc;
}

// ---------------- attention + log_softmax ----------------
__global__ void attn_kernel(const float* __restrict__ Wa,
                            const float* __restrict__ ba,
                            float* __restrict__ out) {
    int gwarp = (blockIdx.x * blockDim.x + threadIdx.x) >> 5;
    int lane  = threadIdx.x & 31;
    if (gwarp >= N_NODES) return;
    const int n = gwarp;

    const float wa0 = Wa[lane];
    const float wa1 = (lane < 8) ? Wa[lane + 32] : 0.f;
    const float bav = ba[0];

    float acc0 = 0.f, acc1 = 0.f;
#pragma unroll
    for (int k = 0; k <= K_HOPS; k++) {
        const float* p = g_xs + ((size_t)k * N_NODES + n) * N_CLASS;
        float v0 = p[lane];
        float v1 = (lane < 8) ? p[lane + 32] : 0.f;
        float dot = v0 * wa0 + v1 * wa1;
#pragma unroll
        for (int off = 16; off > 0; off >>= 1)
            dot += __shfl_xor_sync(0xffffffffu, dot, off);
        float s = 1.f / (1.f + expf(-(dot + bav)));
        acc0 += s * v0;
        acc1 += s * v1;
    }

    float m = acc0;
    if (lane < 8) m = fmaxf(m, acc1);
#pragma unroll
    for (int off = 16; off > 0; off >>= 1)
        m = fmaxf(m, __shfl_xor_sync(0xffffffffu, m, off));

    float se = expf(acc0 - m) + ((lane < 8) ? expf(acc1 - m) : 0.f);
#pragma unroll
    for (int off = 16; off > 0; off >>= 1)
        se += __shfl_xor_sync(0xffffffffu, se, off);

    float lse = logf(se);
    out[(size_t)n * N_CLASS + lane] = acc0 - m - lse;
    if (lane < 8)
        out[(size_t)n * N_CLASS + lane + 32] = acc1 - m - lse;
}

// ---------------- launch (fork-join: CSR chain || dense chain) ----------------
static cudaStream_t g_side    = nullptr;
static cudaEvent_t  g_ev_fork = nullptr;
static cudaEvent_t  g_ev_join = nullptr;
static int          g_inited  = 0;

extern "C" void kernel_launch(void* const* d_in, const int* in_sizes, int n_in,
                              void* d_out, int out_size) {
    const float* feature  = (const float*)d_in[0];
    const int*   edge_row = (const int*)  d_in[1];
    const int*   edge_col = (const int*)  d_in[2];
    const float* edge_w   = (const float*)d_in[3];
    const float* W1       = (const float*)d_in[4];
    const float* b1       = (const float*)d_in[5];
    const float* W2       = (const float*)d_in[6];
    const float* b2       = (const float*)d_in[7];
    const float* Wa       = (const float*)d_in[8];
    const float* ba       = (const float*)d_in[9];
    float*       out      = (float*)d_out;

    if (!g_inited) {
        // One-time host-side infra (streams/events, no device memory). Created
        // on the uncaptured correctness call; reused identically on every call.
        cudaStreamCreateWithFlags(&g_side, cudaStreamNonBlocking);
        cudaEventCreateWithFlags(&g_ev_fork, cudaEventDisableTiming);
        cudaEventCreateWithFlags(&g_ev_join, cudaEventDisableTiming);
        cudaFuncSetAttribute(gemm1_tc_kernel,
                             cudaFuncAttributeMaxDynamicSharedMemorySize, G1_SMEM_TOTAL);
        g_inited = 1;
    }

    const bool fork = (g_side != nullptr) && (g_ev_fork != nullptr) && (g_ev_join != nullptr);
    cudaStream_t cs = fork ? g_side : (cudaStream_t)0;  // CSR chain stream

    if (fork) {
        cudaEventRecord(g_ev_fork, 0);
        cudaStreamWaitEvent(g_side, g_ev_fork, 0);
    }

    // ---- CSR chain (independent of dense path) ----
    zero_count_kernel<<<(N_NODES + 255) / 256, 256, 0, cs>>>();
    hist_kernel<<<(N_EDGES + 255) / 256, 256, 0, cs>>>(edge_row);
    scan_kernel<<<1, 1024, 0, cs>>>();
    scatter_kernel<<<(N_EDGES + 255) / 256, 256, 0, cs>>>(edge_row, edge_col, edge_w);

    if (fork) cudaEventRecord(g_ev_join, g_side);

    // ---- dense chain (legacy stream) ----
    transpose_w1_kernel<<<dim3(N_FEAT / 32, N_HID / 32), dim3(32, 8)>>>(W1);
    gemm1_tc_kernel<<<(N_NODES + 127) / 128, 256, G1_SMEM_TOTAL>>>(feature, b1);
    gemm2_kernel<<<(N_NODES + 63) / 64, 256>>>(W2, b2);

    // ---- join: SpMM needs both CSR and xs plane 0 ----
    if (fork) cudaStreamWaitEvent((cudaStream_t)0, g_ev_join, 0);

    for (int k = 1; k <= K_HOPS; k++)
        spmm_kernel<<<(N_NODES * 10 + 319) / 320, 320>>>(k);

    attn_kernel<<<(N_NODES * 32 + 255) / 256, 256>>>(Wa, ba, out);
}

// round 5
// speedup vs baseline: 1.5591x; 1.0397x over previous
#include <cuda_runtime.h>
#include <cuda_bf16.h>
#include <math.h>
#include <stdint.h>

#define N_NODES 100000
#define N_EDGES 3200000
#define N_FEAT  512
#define N_HID   256
#define N_CLASS 40
#define K_HOPS  10

// tcgen05 only exists in the arch-accelerated target (sm_103a / sm_100a).
// The harness also runs a plain compute_103 ptxas pass, which rejects it.
#if defined(__CUDA_ARCH_FEAT_SM103_ALL) || defined(__CUDA_ARCH_FEAT_SM100_ALL)
#define USE_TCGEN05 1
#else
#define USE_TCGEN05 0
#endif

// ---------------- scratch (no cudaMalloc allowed) ----------------
__device__ float g_h1[(size_t)N_NODES * N_HID];                   // 102.4 MB
__device__ float g_xs[(size_t)(K_HOPS + 1) * N_NODES * N_CLASS];  // 176 MB
__device__ float g_w1t[(size_t)N_HID * N_FEAT];                   // W1^T, 512 KB
__device__ int   g_rowptr[N_NODES + 1];
__device__ int   g_count[N_NODES];
__device__ int   g_cursor[N_NODES];
__device__ int2  g_edge[N_EDGES];                                 // (col, w bits) interleaved

// ================= PTX helpers =================
__device__ __forceinline__ uint32_t smem_to_u32(const void* p) {
    uint32_t a;
    asm("{ .reg .u64 t; cvta.to.shared.u64 t, %1; cvt.u32.u64 %0, t; }"
        : "=r"(a) : "l"(p));
    return a;
}

#if USE_TCGEN05
__device__ __forceinline__ uint32_t elect_one_pred() {
    uint32_t p;
    asm volatile("{\n\t.reg .pred p;\n\telect.sync _|p, 0xFFFFFFFF;\n\t"
                 "selp.b32 %0, 1, 0, p;\n\t}" : "=r"(p));
    return p;
}

#define TCGEN05_ALLOC(smem_addr, nCols) \
    asm volatile("tcgen05.alloc.cta_group::1.sync.aligned.shared::cta.b32 [%0], %1;" \
                 :: "r"((uint32_t)(smem_addr)), "r"((uint32_t)(nCols)) : "memory")
#define TCGEN05_DEALLOC(tmem, nCols) \
    asm volatile("tcgen05.dealloc.cta_group::1.sync.aligned.b32 %0, %1;" \
                 :: "r"(tmem), "r"((uint32_t)(nCols)))
#define TCGEN05_RELINQUISH() \
    asm volatile("tcgen05.relinquish_alloc_permit.cta_group::1.sync.aligned;")
#define TCGEN05_COMMIT(mbar) \
    asm volatile("tcgen05.commit.cta_group::1.mbarrier::arrive::one.shared::cluster.b64 [%0];" \
                 :: "r"((uint32_t)(mbar)) : "memory")
#define TCGEN05_WAIT_LD() \
    asm volatile("tcgen05.wait::ld.sync.aligned;" ::: "memory")
#define TCGEN05_FENCE_AFTER() \
    asm volatile("tcgen05.fence::after_thread_sync;" ::: "memory")
#define TCGEN05_FENCE_BEFORE() \
    asm volatile("tcgen05.fence::before_thread_sync;" ::: "memory")
#define MBARRIER_INIT(mbar, cnt) \
    asm volatile("mbarrier.init.shared.b64 [%0], %1;" \
                 :: "r"((uint32_t)(mbar)), "r"((uint32_t)(cnt)) : "memory")
#define MBARRIER_INVAL(mbar) \
    asm volatile("mbarrier.inval.shared.b64 [%0];" :: "r"((uint32_t)(mbar)) : "memory")
#define FENCE_PROXY_ASYNC() \
    asm volatile("fence.proxy.async.shared::cta;" ::: "memory")

#define MBARRIER_WAIT_PARITY(mbar, parity) do { \
    uint32_t _m = (uint32_t)(mbar); \
    uint32_t _p = (uint32_t)(parity); \
    uint32_t _done; \
    asm volatile("{\n\t.reg .pred p;\n\t" \
        "mbarrier.try_wait.parity.acquire.cta.shared::cta.b64 p, [%1], %2;\n\t" \
        "selp.b32 %0, 1, 0, p;\n\t}" : "=r"(_done) : "r"(_m), "r"(_p) : "memory"); \
    if (!_done) { \
        asm volatile("{\n\t.reg .pred P1;\n\t" \
            "WL_%=:\n\t" \
            "mbarrier.try_wait.parity.acquire.cta.shared::cta.b64 P1, [%0], %1, 0x989680;\n\t" \
            "@P1 bra.uni WD_%=;\n\t" \
            "bra.uni WL_%=;\n\t" \
            "WD_%=:\n\t}" :: "r"(_m), "r"(_p) : "memory"); \
    } \
} while (0)

#define TCGEN05_LD_32X32B_X32(r, tmem_addr) \
    asm volatile( \
        "tcgen05.ld.sync.aligned.32x32b.x32.b32 " \
        "{%0, %1, %2, %3, %4, %5, %6, %7, " \
        " %8, %9, %10, %11, %12, %13, %14, %15, " \
        " %16, %17, %18, %19, %20, %21, %22, %23, " \
        " %24, %25, %26, %27, %28, %29, %30, %31}, [%32];" \
        : "=r"((r)[0]),  "=r"((r)[1]),  "=r"((r)[2]),  "=r"((r)[3]), \
          "=r"((r)[4]),  "=r"((r)[5]),  "=r"((r)[6]),  "=r"((r)[7]), \
          "=r"((r)[8]),  "=r"((r)[9]),  "=r"((r)[10]), "=r"((r)[11]), \
          "=r"((r)[12]), "=r"((r)[13]), "=r"((r)[14]), "=r"((r)[15]), \
          "=r"((r)[16]), "=r"((r)[17]), "=r"((r)[18]), "=r"((r)[19]), \
          "=r"((r)[20]), "=r"((r)[21]), "=r"((r)[22]), "=r"((r)[23]), \
          "=r"((r)[24]), "=r"((r)[25]), "=r"((r)[26]), "=r"((r)[27]), \
          "=r"((r)[28]), "=r"((r)[29]), "=r"((r)[30]), "=r"((r)[31]) \
        : "r"(tmem_addr))

// SW128 K-major descriptor: layout=2 (SW128), version=1, SBO=64, LBO=1
static constexpr uint64_t SMEM_DESC_BASE_SW128 =
    (uint64_t(2) << 61) | (uint64_t(1) << 46) | (uint64_t(64) << 32) | (uint64_t(1) << 16);
#define MAKE_SMEM_DESC(base_addr) \
    (SMEM_DESC_BASE_SW128 | ((uint64_t)((base_addr) >> 4) & 0x3FFF))

// tf32 SS MMA idesc: c=F32 (1<<4), a=TF32 (2<<7), b=TF32 (2<<10),
// N/8 at bits[17:23), M/16 at bits[24:29)
static constexpr uint32_t IDESC_TF32 =
    (1u << 4) | (2u << 7) | (2u << 10) | ((256u / 8u) << 17) | ((128u / 16u) << 24);

__device__ __forceinline__ void mma_tf32_ss(uint32_t d, uint64_t ad, uint64_t bd,
                                            uint32_t idesc, bool acc) {
    uint32_t en = acc ? 1u : 0u;
    asm volatile(
        "{\n\t.reg .pred p;\n\tsetp.ne.u32 p, %5, 0;\n\t"
        "tcgen05.mma.cta_group::1.kind::tf32 [%0], %1, %2, %3, {%4, %4, %4, %4}, p;\n\t}"
        :: "r"(d), "l"(ad), "l"(bd), "r"(idesc), "r"(0u), "r"(en)
        : "memory");
}

__device__ __forceinline__ float to_tf32(float x) {
    uint32_t r;
    asm("cvt.rna.tf32.f32 %0, %1;" : "=r"(r) : "f"(x));
    return __uint_as_float(r);
}
#endif  // USE_TCGEN05

#define SMEM_SWIZZLE_128B(off) ((off) ^ (((off) >> 3) & 0x70))

// ---------------- W1 transpose: g_w1t[n][k] = W1[k][n] ----------------
__global__ void transpose_w1_kernel(const float* __restrict__ W1) {
    __shared__ float t[32][33];
    int bk = blockIdx.x * 32;
    int bn = blockIdx.y * 32;
    int x = threadIdx.x, y = threadIdx.y;
#pragma unroll
    for (int i = 0; i < 32; i += 8)
        t[y + i][x] = W1[(size_t)(bk + y + i) * N_HID + bn + x];
    __syncthreads();
#pragma unroll
    for (int i = 0; i < 32; i += 8)
        g_w1t[(size_t)(bn + y + i) * N_FEAT + bk + x] = t[x][y + i];
}

// ---------------- GEMM1: relu(feature @ W1 + b1) -> g_h1 ----------------
#define G1_CHUNK_K   32
#define G1_NCHUNKS   (N_FEAT / G1_CHUNK_K)      // 16
#define G1_A_BYTES   (128 * 128)
#define G1_B_BYTES   (256 * 128)
#define G1_OFF_A0    1024
#define G1_OFF_A1    (G1_OFF_A0 + G1_A_BYTES)
#define G1_OFF_B0    (G1_OFF_A1 + G1_A_BYTES)
#define G1_OFF_B1    (G1_OFF_B0 + G1_B_BYTES)
#define G1_SMEM_TOTAL (G1_OFF_B1 + G1_B_BYTES)   // 99328

__global__ void __launch_bounds__(256) gemm1_tc_kernel(const float* __restrict__ A,
                                                       const float* __restrict__ bias) {
    extern __shared__ char smem[];
#if USE_TCGEN05
    const uint32_t sb = smem_to_u32(smem);
    const int tid  = threadIdx.x;
    const int wid  = tid >> 5;
    const int lane = tid & 31;
    const int bm   = blockIdx.x * 128;

    if (wid == 4) TCGEN05_ALLOC(sb + 0, 256);
    if (tid == 0) { MBARRIER_INIT(sb + 8, 1); MBARRIER_INIT(sb + 16, 1); }
    __syncthreads();
    uint32_t tmem;
    asm volatile("ld.shared.b32 %0, [%1];" : "=r"(tmem) : "r"(sb + 0));

    const uint32_t aoff[2] = {G1_OFF_A0, G1_OFF_A1};
    const uint32_t boff[2] = {G1_OFF_B0, G1_OFF_B1};

    for (int c = 0; c < G1_NCHUNKS; c++) {
        const int buf = c & 1;
        if (c >= 2) MBARRIER_WAIT_PARITY(sb + 8 + 8 * buf, ((c - 2) >> 1) & 1);

        // A chunk: 128 rows x 8 float4 (k = c*32 .. c*32+31), SW128-swizzled
#pragma unroll
        for (int r = 0; r < 4; r++) {
            int i   = tid + r * 256;
            int row = i >> 3;
            int f4  = i & 7;
            int gm  = bm + row;
            float4 v = make_float4(0.f, 0.f, 0.f, 0.f);
            if (gm < N_NODES)
                v = *(const float4*)(A + (size_t)gm * N_FEAT + c * G1_CHUNK_K + f4 * 4);
            v.x = to_tf32(v.x); v.y = to_tf32(v.y); v.z = to_tf32(v.z); v.w = to_tf32(v.w);
            uint32_t off = SMEM_SWIZZLE_128B((uint32_t)(row * 128 + f4 * 16));
            *(float4*)(smem + aoff[buf] + off) = v;
        }
        // B chunk: 256 n-rows x 8 float4 from W1^T
#pragma unroll
        for (int r = 0; r < 8; r++) {
            int i  = tid + r * 256;
            int n  = i >> 3;
            int f4 = i & 7;
            float4 v = *(const float4*)(g_w1t + (size_t)n * N_FEAT + c * G1_CHUNK_K + f4 * 4);
            v.x = to_tf32(v.x); v.y = to_tf32(v.y); v.z = to_tf32(v.z); v.w = to_tf32(v.w);
            uint32_t off = SMEM_SWIZZLE_128B((uint32_t)(n * 128 + f4 * 16));
            *(float4*)(smem + boff[buf] + off) = v;
        }
        FENCE_PROXY_ASYNC();
        __syncthreads();

        if (wid == 4) {
            if (elect_one_pred()) {
                uint64_t ad = MAKE_SMEM_DESC(sb + aoff[buf]);
                uint64_t bd = MAKE_SMEM_DESC(sb + boff[buf]);
#pragma unroll
                for (int ks = 0; ks < 4; ks++)
                    mma_tf32_ss(tmem, ad + ks * 2, bd + ks * 2, IDESC_TF32,
                                (c > 0) || (ks > 0));
                TCGEN05_COMMIT(sb + 8 + 8 * buf);
            }
        }
    }

    MBARRIER_WAIT_PARITY(sb + 8, 1);
    MBARRIER_WAIT_PARITY(sb + 16, 1);
    TCGEN05_FENCE_AFTER();

    // Epilogue: warps 0-3 read D (128 lanes x 256 cols fp32), bias+relu, store.
    if (wid < 4) {
        const int m = bm + wid * 32 + lane;
#pragma unroll
        for (int b = 0; b < 4; b++) {
            uint32_t r[64];
            TCGEN05_LD_32X32B_X32(r, tmem + b * 64);
            TCGEN05_LD_32X32B_X32(r + 32, tmem + b * 64 + 32);
            TCGEN05_WAIT_LD();
            if (m < N_NODES) {
                float* outp = g_h1 + (size_t)m * N_HID + b * 64;
#pragma unroll
                for (int j = 0; j < 64; j += 4) {
                    float4 o;
                    o.x = fmaxf(__uint_as_float(r[j + 0]) + bias[b * 64 + j + 0], 0.f);
                    o.y = fmaxf(__uint_as_float(r[j + 1]) + bias[b * 64 + j + 1], 0.f);
                    o.z = fmaxf(__uint_as_float(r[j + 2]) + bias[b * 64 + j + 2], 0.f);
                    o.w = fmaxf(__uint_as_float(r[j + 3]) + bias[b * 64 + j + 3], 0.f);
                    *(float4*)(outp + j) = o;
                }
            }
        }
        TCGEN05_FENCE_BEFORE();
    }
    __syncthreads();
    if (tid == 0) { MBARRIER_INVAL(sb + 8); MBARRIER_INVAL(sb + 16); }
    __syncthreads();
    if (wid == 4) { TCGEN05_RELINQUISH(); TCGEN05_DEALLOC(tmem, 256); }

#else  // ---------- SIMT fallback (plain sm_103 JIT path) ----------
    float (*As)[132] = (float(*)[132])smem;
    float (*Bs)[68]  = (float(*)[68])(smem + 16 * 132 * sizeof(float));

    const int tid  = threadIdx.x;
    const int bm   = blockIdx.x * 128;
    const int mIdx = tid >> 4;
    const int nIdx = tid & 15;

    for (int nb = 0; nb < 4; nb++) {
        const int bn = nb * 64;
        float acc[8][4];
#pragma unroll
        for (int i = 0; i < 8; i++)
#pragma unroll
            for (int j = 0; j < 4; j++) acc[i][j] = 0.f;

        for (int kt = 0; kt < N_FEAT; kt += 16) {
#pragma unroll
            for (int r = 0; r < 2; r++) {
                int i  = tid + r * 256;
                int m  = i >> 2;
                int k4 = (i & 3) * 4;
                int gm = bm + m;
                float4 v = make_float4(0.f, 0.f, 0.f, 0.f);
                if (gm < N_NODES)
                    v = *(const float4*)(A + (size_t)gm * N_FEAT + kt + k4);
                As[k4 + 0][m] = v.x;
                As[k4 + 1][m] = v.y;
                As[k4 + 2][m] = v.z;
                As[k4 + 3][m] = v.w;
            }
            {
                int n  = tid >> 2;
                int k4 = (tid & 3) * 4;
                float4 v = *(const float4*)(g_w1t + (size_t)(bn + n) * N_FEAT + kt + k4);
                Bs[k4 + 0][n] = v.x;
                Bs[k4 + 1][n] = v.y;
                Bs[k4 + 2][n] = v.z;
                Bs[k4 + 3][n] = v.w;
            }
            __syncthreads();

#pragma unroll
            for (int k = 0; k < 16; k++) {
                float ra[8], rb[4];
#pragma unroll
                for (int i = 0; i < 8; i++) ra[i] = As[k][mIdx * 8 + i];
#pragma unroll
                for (int j = 0; j < 4; j++) rb[j] = Bs[k][nIdx * 4 + j];
#pragma unroll
                for (int i = 0; i < 8; i++)
#pragma unroll
                    for (int j = 0; j < 4; j++) acc[i][j] += ra[i] * rb[j];
            }
            __syncthreads();
        }

#pragma unroll
        for (int i = 0; i < 8; i++) {
            int gm = bm + mIdx * 8 + i;
            if (gm < N_NODES) {
#pragma unroll
                for (int j = 0; j < 4; j++) {
                    int gn = bn + nIdx * 4 + j;
                    float v = acc[i][j] + bias[gn];
                    g_h1[(size_t)gm * N_HID + gn] = fmaxf(v, 0.f);
                }
            }
        }
    }
#endif
}

// ---------------- GEMM2: g_h1 @ W2 + b2 -> g_xs plane 0 ----------------
__global__ void gemm2_kernel(const float* __restrict__ W2,
                             const float* __restrict__ b2) {
    __shared__ float As[64][65];
    __shared__ float W2s[64 * N_CLASS];

    const int tid = threadIdx.x;
    const int bm  = blockIdx.x * 64;
    const int row = tid >> 2;
    const int q   = tid & 3;

    float acc[10];
#pragma unroll
    for (int j = 0; j < 10; j++) acc[j] = 0.f;

    for (int kb = 0; kb < N_HID; kb += 64) {
#pragma unroll
        for (int r = 0; r < 4; r++) {
            int i  = tid + r * 256;
            int rr = i >> 4;
            int c4 = (i & 15) * 4;
            int gm = bm + rr;
            float4 v = make_float4(0.f, 0.f, 0.f, 0.f);
            if (gm < N_NODES)
                v = *(const float4*)(g_h1 + (size_t)gm * N_HID + kb + c4);
            As[rr][c4 + 0] = v.x;
            As[rr][c4 + 1] = v.y;
            As[rr][c4 + 2] = v.z;
            As[rr][c4 + 3] = v.w;
        }
#pragma unroll
        for (int r = 0; r < 10; r++) {
            int e = tid + r * 256;
            W2s[e] = W2[(size_t)kb * N_CLASS + e];
        }
        __syncthreads();

#pragma unroll 4
        for (int k = 0; k < 64; k++) {
            float a = As[row][k];
#pragma unroll
            for (int j = 0; j < 10; j++)
                acc[j] += a * W2s[k * N_CLASS + q * 10 + j];
        }
        __syncthreads();
    }

    int gm = bm + row;
    if (gm < N_NODES) {
#pragma unroll
        for (int j = 0; j < 10; j++)
            g_xs[(size_t)gm * N_CLASS + q * 10 + j] = acc[j] + b2[q * 10 + j];
    }
}

// ---------------- CSR build ----------------
__global__ void zero_count_kernel() {
    int i = blockIdx.x * blockDim.x + threadIdx.x;
    if (i < N_NODES) g_count[i] = 0;
}

__global__ void hist_kernel(const int* __restrict__ edge_row) {
    int e = blockIdx.x * blockDim.x + threadIdx.x;
    if (e < N_EDGES) atomicAdd(&g_count[edge_row[e]], 1);
}

__global__ void scan_kernel() {
    __shared__ int warp_sums[32];
    __shared__ int carry_s;
    const int tid = threadIdx.x, lane = tid & 31, wid = tid >> 5;
    if (tid == 0) { carry_s = 0; g_rowptr[0] = 0; }
    __syncthreads();

    for (int base = 0; base < N_NODES; base += 1024) {
        int i = base + tid;
        int v = (i < N_NODES) ? g_count[i] : 0;
        int x = v;
#pragma unroll
        for (int off = 1; off < 32; off <<= 1) {
            int y = __shfl_up_sync(0xffffffffu, x, off);
            if (lane >= off) x += y;
        }
        if (lane == 31) warp_sums[wid] = x;
        __syncthreads();
        if (wid == 0) {
            int s = warp_sums[lane];
#pragma unroll
            for (int off = 1; off < 32; off <<= 1) {
                int y = __shfl_up_sync(0xffffffffu, s, off);
                if (lane >= off) s += y;
            }
            warp_sums[lane] = s;
        }
        __syncthreads();
        int incl = x + ((wid > 0) ? warp_sums[wid - 1] : 0) + carry_s;
        if (i < N_NODES) {
            g_rowptr[i + 1] = incl;
            g_cursor[i]     = incl - v;
        }
        __syncthreads();
        if (tid == 1023) carry_s = incl;
        __syncthreads();
    }
}

__global__ void scatter_kernel(const int* __restrict__ edge_row,
                               const int* __restrict__ edge_col,
                               const float* __restrict__ edge_w) {
    int e = blockIdx.x * blockDim.x + threadIdx.x;
    if (e < N_EDGES) {
        int r = edge_row[e];
        int p = atomicAdd(&g_cursor[r], 1);
        g_edge[p] = make_int2(edge_col[e], __float_as_int(edge_w[e]));
    }
}

// ---------------- SpMM hop: xs[hop] = A_sparse @ xs[hop-1] ----------------
// 10 threads per row; edge (col,w) pairs batched 4 at a time so the four
// 16B gathers are independent (MLP>=4 hides L2 latency).
__global__ void __launch_bounds__(320) spmm_kernel(int hop) {
    const float* __restrict__ xin  = g_xs + (size_t)(hop - 1) * N_NODES * N_CLASS;
    float* __restrict__       xout = g_xs + (size_t)hop * N_NODES * N_CLASS;

    int t    = blockIdx.x * blockDim.x + threadIdx.x;
    int row  = t / 10;
    int lane = t - row * 10;
    if (row >= N_NODES) return;

    const int s = g_rowptr[row];
    const int e = g_rowptr[row + 1];
    float4 acc = make_float4(0.f, 0.f, 0.f, 0.f);

    int i = s;
    for (; i + 4 <= e; i += 4) {
        int2 e0 = g_edge[i + 0];
        int2 e1 = g_edge[i + 1];
        int2 e2 = g_edge[i + 2];
        int2 e3 = g_edge[i + 3];
        float4 v0 = *(const float4*)(xin + (size_t)e0.x * N_CLASS + lane * 4);
        float4 v1 = *(const float4*)(xin + (size_t)e1.x * N_CLASS + lane * 4);
        float4 v2 = *(const float4*)(xin + (size_t)e2.x * N_CLASS + lane * 4);
        float4 v3 = *(const float4*)(xin + (size_t)e3.x * N_CLASS + lane * 4);
        float w0 = __int_as_float(e0.y);
        float w1 = __int_as_float(e1.y);
        float w2 = __int_as_float(e2.y);
        float w3 = __int_as_float(e3.y);
        acc.x += w0 * v0.x; acc.y += w0 * v0.y; acc.z += w0 * v0.z; acc.w += w0 * v0.w;
        acc.x += w1 * v1.x; acc.y += w1 * v1.y; acc.z += w1 * v1.z; acc.w += w1 * v1.w;
        acc.x += w2 * v2.x; acc.y += w2 * v2.y; acc.z += w2 * v2.z; acc.w += w2 * v2.w;
        acc.x += w3 * v3.x; acc.y += w3 * v3.y; acc.z += w3 * v3.z; acc.w += w3 * v3.w;
    }
    for (; i < e; i++) {
        int2  ed = g_edge[i];
        float w  = __int_as_float(ed.y);
        float4 v = *(const float4*)(xin + (size_t)ed.x * N_CLASS + lane * 4);
        acc.x += w * v.x; acc.y += w * v.y; acc.z += w * v.z; acc.w += w * v.w;
    }
    *(float4*)(xout + (size_t)row * N_CLASS + lane * 4) = acc;
}

// ---------------- attention + log_softmax ----------------
__global__ void attn_kernel(const float* __restrict__ Wa,
                            const float* __restrict__ ba,
                            float* __restrict__ out) {
    int gwarp = (blockIdx.x * blockDim.x + threadIdx.x) >> 5;
    int lane  = threadIdx.x & 31;
    if (gwarp >= N_NODES) return;
    const int n = gwarp;

    const float wa0 = Wa[lane];
    const float wa1 = (lane < 8) ? Wa[lane + 32] : 0.f;
    const float bav = ba[0];

    float acc0 = 0.f, acc1 = 0.f;
#pragma unroll
    for (int k = 0; k <= K_HOPS; k++) {
        const float* p = g_xs + ((size_t)k * N_NODES + n) * N_CLASS;
        float v0 = p[lane];
        float v1 = (lane < 8) ? p[lane + 32] : 0.f;
        float dot = v0 * wa0 + v1 * wa1;
#pragma unroll
        for (int off = 16; off > 0; off >>= 1)
            dot += __shfl_xor_sync(0xffffffffu, dot, off);
        float s = 1.f / (1.f + expf(-(dot + bav)));
        acc0 += s * v0;
        acc1 += s * v1;
    }

    float m = acc0;
    if (lane < 8) m = fmaxf(m, acc1);
#pragma unroll
    for (int off = 16; off > 0; off >>= 1)
        m = fmaxf(m, __shfl_xor_sync(0xffffffffu, m, off));

    float se = expf(acc0 - m) + ((lane < 8) ? expf(acc1 - m) : 0.f);
#pragma unroll
    for (int off = 16; off > 0; off >>= 1)
        se += __shfl_xor_sync(0xffffffffu, se, off);

    float lse = logf(se);
    out[(size_t)n * N_CLASS + lane] = acc0 - m - lse;
    if (lane < 8)
        out[(size_t)n * N_CLASS + lane + 32] = acc1 - m - lse;
}

// ---------------- launch (fork-join: CSR chain || dense chain) ----------------
static cudaStream_t g_side    = nullptr;
static cudaEvent_t  g_ev_fork = nullptr;
static cudaEvent_t  g_ev_join = nullptr;
static int          g_inited  = 0;

extern "C" void kernel_launch(void* const* d_in, const int* in_sizes, int n_in,
                              void* d_out, int out_size) {
    const float* feature  = (const float*)d_in[0];
    const int*   edge_row = (const int*)  d_in[1];
    const int*   edge_col = (const int*)  d_in[2];
    const float* edge_w   = (const float*)d_in[3];
    const float* W1       = (const float*)d_in[4];
    const float* b1       = (const float*)d_in[5];
    const float* W2       = (const float*)d_in[6];
    const float* b2       = (const float*)d_in[7];
    const float* Wa       = (const float*)d_in[8];
    const float* ba       = (const float*)d_in[9];
    float*       out      = (float*)d_out;

    if (!g_inited) {
        cudaStreamCreateWithFlags(&g_side, cudaStreamNonBlocking);
        cudaEventCreateWithFlags(&g_ev_fork, cudaEventDisableTiming);
        cudaEventCreateWithFlags(&g_ev_join, cudaEventDisableTiming);
        cudaFuncSetAttribute(gemm1_tc_kernel,
                             cudaFuncAttributeMaxDynamicSharedMemorySize, G1_SMEM_TOTAL);
        g_inited = 1;
    }

    const bool fork = (g_side != nullptr) && (g_ev_fork != nullptr) && (g_ev_join != nullptr);
    cudaStream_t cs = fork ? g_side : (cudaStream_t)0;

    if (fork) {
        cudaEventRecord(g_ev_fork, 0);
        cudaStreamWaitEvent(g_side, g_ev_fork, 0);
    }

    // ---- CSR chain (independent of dense path) ----
    zero_count_kernel<<<(N_NODES + 255) / 256, 256, 0, cs>>>();
    hist_kernel<<<(N_EDGES + 255) / 256, 256, 0, cs>>>(edge_row);
    scan_kernel<<<1, 1024, 0, cs>>>();
    scatter_kernel<<<(N_EDGES + 255) / 256, 256, 0, cs>>>(edge_row, edge_col, edge_w);

    if (fork) cudaEventRecord(g_ev_join, g_side);

    // ---- dense chain (legacy stream) ----
    transpose_w1_kernel<<<dim3(N_FEAT / 32, N_HID / 32), dim3(32, 8)>>>(W1);
    gemm1_tc_kernel<<<(N_NODES + 127) / 128, 256, G1_SMEM_TOTAL>>>(feature, b1);
    gemm2_kernel<<<(N_NODES + 63) / 64, 256>>>(W2, b2);

    // ---- join: SpMM needs both CSR and xs plane 0 ----
    if (fork) cudaStreamWaitEvent((cudaStream_t)0, g_ev_join, 0);

    for (int k = 1; k <= K_HOPS; k++)
        spmm_kernel<<<(N_NODES * 10 + 319) / 320, 320>>>(k);

    attn_kernel<<<(N_NODES * 32 + 255) / 256, 256>>>(Wa, ba, out);
}